// round 1
// baseline (speedup 1.0000x reference)
#include <cuda_runtime.h>
#include <math.h>

// ---------------- problem constants ----------------
namespace {
constexpr int BATCH = 2;
constexpr int SEQ   = 1024;
constexpr int DIM   = 768;
constexpr int NH    = 12;
constexpr int HD    = 64;
constexpr int FFD   = 3072;
constexpr int NE    = 4;
constexpr int NTOK  = BATCH * SEQ;   // 2048
constexpr int BHZ   = BATCH * NH;    // 24
constexpr float EPSZ  = 1e-5f;
constexpr float EPSLN = 1e-5f;
}

// ---------------- scratch (static device memory; no runtime allocs) ----------------
__device__ float g_Q[NTOK * DIM];
__device__ float g_K[NTOK * DIM];
__device__ float g_V[NTOK * DIM];
__device__ float g_P[(size_t)BHZ * SEQ * SEQ];      // logits -> probs (in place)
__device__ float g_attn[NTOK * DIM];                // attention output (pre O-proj)
__device__ float g_attno[NTOK * DIM];               // O-proj output
__device__ float g_x[NTOK * DIM];                   // after LN1
__device__ float g_ff[NTOK * DIM];                  // MoE output accumulator
__device__ float g_H1[(size_t)NE * NTOK * FFD];     // expert hidden activations (compact)
__device__ int   g_cnt[NE];
__device__ int   g_list[NE * NTOK];
__device__ float g_wgt[NE * NTOK];

// ---------------- reductions (blockDim == 256) ----------------
__device__ __forceinline__ float blockReduceSum(float v) {
    __shared__ float red[8];
    int lane = threadIdx.x & 31, wid = threadIdx.x >> 5;
#pragma unroll
    for (int o = 16; o > 0; o >>= 1) v += __shfl_xor_sync(0xffffffffu, v, o);
    __syncthreads();
    if (lane == 0) red[wid] = v;
    __syncthreads();
    float r = (lane < 8) ? red[lane] : 0.f;
#pragma unroll
    for (int o = 16; o > 0; o >>= 1) r += __shfl_xor_sync(0xffffffffu, r, o);
    return r;
}

__device__ __forceinline__ float blockReduceMax(float v) {
    __shared__ float redm[8];
    int lane = threadIdx.x & 31, wid = threadIdx.x >> 5;
#pragma unroll
    for (int o = 16; o > 0; o >>= 1) v = fmaxf(v, __shfl_xor_sync(0xffffffffu, v, o));
    __syncthreads();
    if (lane == 0) redm[wid] = v;
    __syncthreads();
    float r = (lane < 8) ? redm[lane] : -1e30f;
#pragma unroll
    for (int o = 16; o > 0; o >>= 1) r = fmaxf(r, __shfl_xor_sync(0xffffffffu, r, o));
    return r;
}

// ---------------- zero scratch used with atomics ----------------
__global__ void zero_kernel() {
    int i = blockIdx.x * 256 + threadIdx.x;
    if (i < NTOK * DIM) g_ff[i] = 0.f;
    if (i < NE) g_cnt[i] = 0;
}

// ---------------- generic NT GEMM: C = A * B^T + bias ----------------
// A[M,K] lda, B[N,K] ldb (both K-contiguous), C[M,N] ldc. 256 threads, 64x64x32 tiles.
__global__ void gemm_nt_bias(const float* __restrict__ A, const float* __restrict__ Bm,
                             const float* __restrict__ bias, float* __restrict__ C,
                             int M, int N, int K, int lda, int ldb, int ldc) {
    __shared__ float As[32][65];
    __shared__ float Bs[32][65];
    int tid = threadIdx.x;
    int m0 = blockIdx.y * 64, n0 = blockIdx.x * 64;
    int tx = tid & 15, ty = tid >> 4;
    float acc[4][4] = {};
    for (int kt = 0; kt < K; kt += 32) {
#pragma unroll
        for (int i = 0; i < 8; i++) {
            int idx = tid + i * 256;
            int m = idx >> 5, k = idx & 31;
            As[k][m] = (m0 + m < M) ? A[(size_t)(m0 + m) * lda + kt + k] : 0.f;
        }
#pragma unroll
        for (int i = 0; i < 8; i++) {
            int idx = tid + i * 256;
            int n = idx >> 5, k = idx & 31;
            Bs[k][n] = (n0 + n < N) ? Bm[(size_t)(n0 + n) * ldb + kt + k] : 0.f;
        }
        __syncthreads();
#pragma unroll
        for (int kk = 0; kk < 32; kk++) {
            float av[4], bv[4];
#pragma unroll
            for (int i = 0; i < 4; i++) av[i] = As[kk][ty * 4 + i];
#pragma unroll
            for (int j = 0; j < 4; j++) bv[j] = Bs[kk][tx * 4 + j];
#pragma unroll
            for (int i = 0; i < 4; i++)
#pragma unroll
                for (int j = 0; j < 4; j++) acc[i][j] += av[i] * bv[j];
        }
        __syncthreads();
    }
#pragma unroll
    for (int i = 0; i < 4; i++) {
        int row = m0 + ty * 4 + i;
        if (row < M) {
#pragma unroll
            for (int j = 0; j < 4; j++) {
                int col = n0 + tx * 4 + j;
                if (col < N) C[(size_t)row * ldc + col] = acc[i][j] + (bias ? bias[col] : 0.f);
            }
        }
    }
}

// ---------------- batched QK^T: logits[z,q,k] = scale * sum_d Q[b,q,h,d]K[b,k,h,d] ----------------
__global__ void qk_kernel(const float* __restrict__ Q, const float* __restrict__ Kt, float scale) {
    int z = blockIdx.z, b = z / NH, h = z % NH;
    const float* Ab = Q + (size_t)b * SEQ * DIM + h * HD;
    const float* Bb = Kt + (size_t)b * SEQ * DIM + h * HD;
    float* Cb = g_P + (size_t)z * SEQ * SEQ;
    __shared__ float As[32][65];
    __shared__ float Bs[32][65];
    int tid = threadIdx.x;
    int m0 = blockIdx.y * 64, n0 = blockIdx.x * 64;
    int tx = tid & 15, ty = tid >> 4;
    float acc[4][4] = {};
    for (int kt = 0; kt < HD; kt += 32) {
#pragma unroll
        for (int i = 0; i < 8; i++) {
            int idx = tid + i * 256;
            int m = idx >> 5, k = idx & 31;
            As[k][m] = Ab[(size_t)(m0 + m) * DIM + kt + k];
        }
#pragma unroll
        for (int i = 0; i < 8; i++) {
            int idx = tid + i * 256;
            int n = idx >> 5, k = idx & 31;
            Bs[k][n] = Bb[(size_t)(n0 + n) * DIM + kt + k];
        }
        __syncthreads();
#pragma unroll
        for (int kk = 0; kk < 32; kk++) {
            float av[4], bv[4];
#pragma unroll
            for (int i = 0; i < 4; i++) av[i] = As[kk][ty * 4 + i];
#pragma unroll
            for (int j = 0; j < 4; j++) bv[j] = Bs[kk][tx * 4 + j];
#pragma unroll
            for (int i = 0; i < 4; i++)
#pragma unroll
                for (int j = 0; j < 4; j++) acc[i][j] += av[i] * bv[j];
        }
        __syncthreads();
    }
#pragma unroll
    for (int i = 0; i < 4; i++) {
        int row = m0 + ty * 4 + i;
#pragma unroll
        for (int j = 0; j < 4; j++) {
            int col = n0 + tx * 4 + j;
            Cb[(size_t)row * SEQ + col] = acc[i][j] * scale;
        }
    }
}

// ---------------- per-row zscore (ddof=1) + gamma + softmax, in place ----------------
__global__ void zsoftmax_kernel(const float* __restrict__ gamma) {
    int q = blockIdx.x, z = blockIdx.y;
    float* row = g_P + ((size_t)z * SEQ + q) * SEQ;
    int tid = threadIdx.x;
    float v[4];
#pragma unroll
    for (int i = 0; i < 4; i++) v[i] = row[tid + i * 256];
    float mean = blockReduceSum(v[0] + v[1] + v[2] + v[3]) * (1.f / SEQ);
    float sq = 0.f;
#pragma unroll
    for (int i = 0; i < 4; i++) { v[i] -= mean; sq += v[i] * v[i]; }
    float var = blockReduceSum(sq) * (1.f / (SEQ - 1));
    float inv = (*gamma) / (sqrtf(var) + EPSZ);
    float mx = -1e30f;
#pragma unroll
    for (int i = 0; i < 4; i++) { v[i] *= inv; mx = fmaxf(mx, v[i]); }
    mx = blockReduceMax(mx);
    float es = 0.f;
#pragma unroll
    for (int i = 0; i < 4; i++) { v[i] = __expf(v[i] - mx); es += v[i]; }
    es = blockReduceSum(es);
    float r = 1.f / es;
#pragma unroll
    for (int i = 0; i < 4; i++) row[tid + i * 256] = v[i] * r;
}

// ---------------- batched P @ V: attn[b,q,h,d] = sum_k P[z,q,k] V[b,k,h,d] ----------------
__global__ void pv_kernel(const float* __restrict__ V) {
    int z = blockIdx.z, b = z / NH, h = z % NH;
    const float* A = g_P + (size_t)z * SEQ * SEQ;
    const float* Bb = V + (size_t)b * SEQ * DIM + h * HD;
    float* Cb = g_attn + (size_t)b * SEQ * DIM + h * HD;
    __shared__ float As[32][65];
    __shared__ float Bs[32][65];
    int tid = threadIdx.x;
    int m0 = blockIdx.y * 64;
    int tx = tid & 15, ty = tid >> 4;
    float acc[4][4] = {};
    for (int kt = 0; kt < SEQ; kt += 32) {
#pragma unroll
        for (int i = 0; i < 8; i++) {
            int idx = tid + i * 256;
            int m = idx >> 5, k = idx & 31;
            As[k][m] = A[(size_t)(m0 + m) * SEQ + kt + k];
        }
#pragma unroll
        for (int i = 0; i < 8; i++) {
            int idx = tid + i * 256;
            int n = idx & 63, k = idx >> 6;
            Bs[k][n] = Bb[(size_t)(kt + k) * DIM + n];
        }
        __syncthreads();
#pragma unroll
        for (int kk = 0; kk < 32; kk++) {
            float av[4], bv[4];
#pragma unroll
            for (int i = 0; i < 4; i++) av[i] = As[kk][ty * 4 + i];
#pragma unroll
            for (int j = 0; j < 4; j++) bv[j] = Bs[kk][tx * 4 + j];
#pragma unroll
            for (int i = 0; i < 4; i++)
#pragma unroll
                for (int j = 0; j < 4; j++) acc[i][j] += av[i] * bv[j];
        }
        __syncthreads();
    }
#pragma unroll
    for (int i = 0; i < 4; i++) {
        int row = m0 + ty * 4 + i;
#pragma unroll
        for (int j = 0; j < 4; j++) {
            int col = tx * 4 + j;
            Cb[(size_t)row * DIM + col] = acc[i][j];
        }
    }
}

// ---------------- out = LayerNorm(a + b) ----------------
__global__ void add_ln_kernel(const float* __restrict__ a, const float* __restrict__ b,
                              const float* __restrict__ g, const float* __restrict__ be,
                              float* __restrict__ out) {
    int t = blockIdx.x, tid = threadIdx.x;
    const float* ar = a + (size_t)t * DIM;
    const float* br = b + (size_t)t * DIM;
    float v[3];
#pragma unroll
    for (int i = 0; i < 3; i++) v[i] = ar[tid + i * 256] + br[tid + i * 256];
    float mean = blockReduceSum(v[0] + v[1] + v[2]) * (1.f / DIM);
    float sq = 0.f;
#pragma unroll
    for (int i = 0; i < 3; i++) { v[i] -= mean; sq += v[i] * v[i]; }
    float var = blockReduceSum(sq) * (1.f / DIM);
    float r = rsqrtf(var + EPSLN);
#pragma unroll
    for (int i = 0; i < 3; i++) {
        int c = tid + i * 256;
        out[(size_t)t * DIM + c] = v[i] * r * g[c] + be[c];
    }
}

// ---------------- gating: softmax over E=4, top-2, build routing lists ----------------
__global__ void gate_kernel(const float* __restrict__ x, const float* __restrict__ Wg,
                            const float* __restrict__ bg) {
    int gwarp = (blockIdx.x * blockDim.x + threadIdx.x) >> 5;
    int lane = threadIdx.x & 31;
    if (gwarp >= NTOK) return;
    const float* xr = x + (size_t)gwarp * DIM;
    float s0 = 0, s1 = 0, s2 = 0, s3 = 0;
    for (int d = lane; d < DIM; d += 32) {
        float xv = xr[d];
        s0 += xv * Wg[d];
        s1 += xv * Wg[DIM + d];
        s2 += xv * Wg[2 * DIM + d];
        s3 += xv * Wg[3 * DIM + d];
    }
#pragma unroll
    for (int o = 16; o > 0; o >>= 1) {
        s0 += __shfl_xor_sync(0xffffffffu, s0, o);
        s1 += __shfl_xor_sync(0xffffffffu, s1, o);
        s2 += __shfl_xor_sync(0xffffffffu, s2, o);
        s3 += __shfl_xor_sync(0xffffffffu, s3, o);
    }
    if (lane == 0) {
        float s[4] = {s0 + bg[0], s1 + bg[1], s2 + bg[2], s3 + bg[3]};
        float mx = fmaxf(fmaxf(s[0], s[1]), fmaxf(s[2], s[3]));
        float p[4], sum = 0.f;
#pragma unroll
        for (int e = 0; e < 4; e++) { p[e] = expf(s[e] - mx); sum += p[e]; }
        float r = 1.f / sum;
#pragma unroll
        for (int e = 0; e < 4; e++) p[e] *= r;
        int i1 = 0;
#pragma unroll
        for (int e = 1; e < 4; e++) if (p[e] > p[i1]) i1 = e;
        int i2 = (i1 == 0) ? 1 : 0;
#pragma unroll
        for (int e = 0; e < 4; e++) if (e != i1 && p[e] > p[i2]) i2 = e;
        int slot = atomicAdd(&g_cnt[i1], 1);
        g_list[i1 * NTOK + slot] = gwarp;
        g_wgt[i1 * NTOK + slot] = p[i1];
        slot = atomicAdd(&g_cnt[i2], 1);
        g_list[i2 * NTOK + slot] = gwarp;
        g_wgt[i2 * NTOK + slot] = p[i2];
    }
}

// ---------------- expert FF1: H1[e,i,:] = relu(x[list] @ W1[e] + b1[e]) ----------------
__global__ void ff1_kernel(const float* __restrict__ x, const float* __restrict__ W1,
                           const float* __restrict__ b1) {
    int e = blockIdx.z;
    int cnt = g_cnt[e];
    int m0 = blockIdx.y * 64;
    if (m0 >= cnt) return;
    int n0 = blockIdx.x * 64;
    const float* Wb = W1 + (size_t)e * DIM * FFD;
    const float* bb = b1 + e * FFD;
    const int* list = g_list + e * NTOK;
    float* Hout = g_H1 + (size_t)e * NTOK * FFD;
    __shared__ float As[32][65];
    __shared__ float Bs[32][65];
    __shared__ int rows[64];
    int tid = threadIdx.x;
    if (tid < 64) rows[tid] = (m0 + tid < cnt) ? list[m0 + tid] : -1;
    __syncthreads();
    int tx = tid & 15, ty = tid >> 4;
    float acc[4][4] = {};
    for (int kt = 0; kt < DIM; kt += 32) {
#pragma unroll
        for (int i = 0; i < 8; i++) {
            int idx = tid + i * 256;
            int m = idx >> 5, k = idx & 31;
            int rr = rows[m];
            As[k][m] = (rr >= 0) ? x[(size_t)rr * DIM + kt + k] : 0.f;
        }
#pragma unroll
        for (int i = 0; i < 8; i++) {
            int idx = tid + i * 256;
            int n = idx & 63, k = idx >> 6;
            Bs[k][n] = Wb[(size_t)(kt + k) * FFD + n0 + n];
        }
        __syncthreads();
#pragma unroll
        for (int kk = 0; kk < 32; kk++) {
            float av[4], bv[4];
#pragma unroll
            for (int i = 0; i < 4; i++) av[i] = As[kk][ty * 4 + i];
#pragma unroll
            for (int j = 0; j < 4; j++) bv[j] = Bs[kk][tx * 4 + j];
#pragma unroll
            for (int i = 0; i < 4; i++)
#pragma unroll
                for (int j = 0; j < 4; j++) acc[i][j] += av[i] * bv[j];
        }
        __syncthreads();
    }
#pragma unroll
    for (int i = 0; i < 4; i++) {
        int m = m0 + ty * 4 + i;
        if (m < cnt) {
#pragma unroll
            for (int j = 0; j < 4; j++) {
                int c = n0 + tx * 4 + j;
                Hout[(size_t)m * FFD + c] = fmaxf(acc[i][j] + bb[c], 0.f);
            }
        }
    }
}

// ---------------- expert FF2: ff[token] += w * (H1 @ W2[e] + b2[e]) ----------------
__global__ void ff2_kernel(const float* __restrict__ W2, const float* __restrict__ b2) {
    int e = blockIdx.z;
    int cnt = g_cnt[e];
    int m0 = blockIdx.y * 64;
    if (m0 >= cnt) return;
    int n0 = blockIdx.x * 64;
    const float* A = g_H1 + (size_t)e * NTOK * FFD;
    const float* Wb = W2 + (size_t)e * FFD * DIM;
    const float* bb = b2 + e * DIM;
    const int* list = g_list + e * NTOK;
    const float* wgt = g_wgt + e * NTOK;
    __shared__ float As[32][65];
    __shared__ float Bs[32][65];
    __shared__ int rows[64];
    __shared__ float ws[64];
    int tid = threadIdx.x;
    if (tid < 64) {
        int m = m0 + tid;
        rows[tid] = (m < cnt) ? list[m] : -1;
        ws[tid] = (m < cnt) ? wgt[m] : 0.f;
    }
    __syncthreads();
    int tx = tid & 15, ty = tid >> 4;
    float acc[4][4] = {};
    for (int kt = 0; kt < FFD; kt += 32) {
#pragma unroll
        for (int i = 0; i < 8; i++) {
            int idx = tid + i * 256;
            int m = idx >> 5, k = idx & 31;
            As[k][m] = (m0 + m < cnt) ? A[(size_t)(m0 + m) * FFD + kt + k] : 0.f;
        }
#pragma unroll
        for (int i = 0; i < 8; i++) {
            int idx = tid + i * 256;
            int n = idx & 63, k = idx >> 6;
            Bs[k][n] = Wb[(size_t)(kt + k) * DIM + n0 + n];
        }
        __syncthreads();
#pragma unroll
        for (int kk = 0; kk < 32; kk++) {
            float av[4], bv[4];
#pragma unroll
            for (int i = 0; i < 4; i++) av[i] = As[kk][ty * 4 + i];
#pragma unroll
            for (int j = 0; j < 4; j++) bv[j] = Bs[kk][tx * 4 + j];
#pragma unroll
            for (int i = 0; i < 4; i++)
#pragma unroll
                for (int j = 0; j < 4; j++) acc[i][j] += av[i] * bv[j];
        }
        __syncthreads();
    }
#pragma unroll
    for (int i = 0; i < 4; i++) {
        int m = m0 + ty * 4 + i;
        if (m < cnt) {
            int t = rows[ty * 4 + i];
            float w = ws[ty * 4 + i];
#pragma unroll
            for (int j = 0; j < 4; j++) {
                int c = n0 + tx * 4 + j;
                atomicAdd(&g_ff[(size_t)t * DIM + c], w * (acc[i][j] + bb[c]));
            }
        }
    }
}

// ---------------- launch ----------------
extern "C" void kernel_launch(void* const* d_in, const int* in_sizes, int n_in,
                              void* d_out, int out_size) {
    const float* src  = (const float*)d_in[0];
    // d_in[1] = frac (unused: add_frac_bias=False path)
    const float* Wq = (const float*)d_in[2];
    const float* bq = (const float*)d_in[3];
    const float* Wk = (const float*)d_in[4];
    const float* bk = (const float*)d_in[5];
    const float* Wv = (const float*)d_in[6];
    const float* bv = (const float*)d_in[7];
    const float* Wo = (const float*)d_in[8];
    const float* bo = (const float*)d_in[9];
    const float* gamma = (const float*)d_in[10];
    const float* ln1g = (const float*)d_in[11];
    const float* ln1b = (const float*)d_in[12];
    const float* ln2g = (const float*)d_in[13];
    const float* ln2b = (const float*)d_in[14];
    const float* Wg = (const float*)d_in[15];
    const float* bg = (const float*)d_in[16];
    const float* W1 = (const float*)d_in[17];
    const float* b1 = (const float*)d_in[18];
    const float* W2 = (const float*)d_in[19];
    const float* b2 = (const float*)d_in[20];
    float* out = (float*)d_out;

    float *Qp, *Kp, *Vp, *attnp, *attnop, *xp, *ffp;
    cudaGetSymbolAddress((void**)&Qp, g_Q);
    cudaGetSymbolAddress((void**)&Kp, g_K);
    cudaGetSymbolAddress((void**)&Vp, g_V);
    cudaGetSymbolAddress((void**)&attnp, g_attn);
    cudaGetSymbolAddress((void**)&attnop, g_attno);
    cudaGetSymbolAddress((void**)&xp, g_x);
    cudaGetSymbolAddress((void**)&ffp, g_ff);

    // zero ff accumulator + routing counters
    zero_kernel<<<(NTOK * DIM + 255) / 256, 256>>>();

    // QKV projections: [2048,768] x [768,768]^T
    dim3 gproj(DIM / 64, NTOK / 64);
    gemm_nt_bias<<<gproj, 256>>>(src, Wq, bq, Qp, NTOK, DIM, DIM, DIM, DIM, DIM);
    gemm_nt_bias<<<gproj, 256>>>(src, Wk, bk, Kp, NTOK, DIM, DIM, DIM, DIM, DIM);
    gemm_nt_bias<<<gproj, 256>>>(src, Wv, bv, Vp, NTOK, DIM, DIM, DIM, DIM, DIM);

    // logits = scale * Q K^T  (scale folded in before zscore, matching eps semantics)
    qk_kernel<<<dim3(SEQ / 64, SEQ / 64, BHZ), 256>>>(Qp, Kp, 0.125f);

    // zscore (ddof=1) + gamma + softmax, in place
    zsoftmax_kernel<<<dim3(SEQ, BHZ), 256>>>(gamma);

    // attn = P @ V
    pv_kernel<<<dim3(1, SEQ / 64, BHZ), 256>>>(Vp);

    // O projection
    gemm_nt_bias<<<gproj, 256>>>(attnp, Wo, bo, attnop, NTOK, DIM, DIM, DIM, DIM, DIM);

    // x = LN1(src + attn_out)
    add_ln_kernel<<<NTOK, 256>>>(src, attnop, ln1g, ln1b, xp);

    // gating + routing
    gate_kernel<<<NTOK * 32 / 256, 256>>>(xp, Wg, bg);

    // expert FFN (sparse top-2)
    ff1_kernel<<<dim3(FFD / 64, NTOK / 64, NE), 256>>>(xp, W1, b1);
    ff2_kernel<<<dim3(DIM / 64, NTOK / 64, NE), 256>>>(W2, b2);

    // out = LN2(x + ff)
    add_ln_kernel<<<NTOK, 256>>>(xp, ffp, ln2g, ln2b, out);
}

// round 2
// speedup vs baseline: 1.6286x; 1.6286x over previous
#include <cuda_runtime.h>
#include <math.h>
#include <stdint.h>

// ---------------- problem constants ----------------
namespace {
constexpr int BATCH = 2;
constexpr int SEQ   = 1024;
constexpr int DIM   = 768;
constexpr int NH    = 12;
constexpr int HD    = 64;
constexpr int FFD   = 3072;
constexpr int NE    = 4;
constexpr int NTOK  = BATCH * SEQ;   // 2048
constexpr int BHZ   = BATCH * NH;    // 24
constexpr float EPSZ  = 1e-5f;
constexpr float EPSLN = 1e-5f;
constexpr int ALD = 20;  // As row pitch (floats) - conflict-free for frag reads + f4 STS
constexpr int BLD = 20;  // Bs row pitch
}

// ---------------- scratch (static device memory) ----------------
__device__ float g_Q[NTOK * DIM];
__device__ float g_K[NTOK * DIM];
__device__ float g_Vt[BHZ * HD * SEQ];              // V transposed: [b][h][d][t]
__device__ float g_P[(size_t)BHZ * SEQ * SEQ];      // logits -> probs (in place)
__device__ float g_attn[NTOK * DIM];                // attention output (pre O-proj)
__device__ float g_attno[NTOK * DIM];               // O-proj output
__device__ float g_x[NTOK * DIM];                   // after LN1
__device__ float g_H1[(size_t)NE * NTOK * FFD];     // expert hidden (compact rows)
__device__ float g_Y[(size_t)NE * NTOK * DIM];      // expert FF2 out (compact rows)
__device__ float g_W1t[(size_t)NE * FFD * DIM];     // W1 transposed [e][ff][d]
__device__ float g_W2t[(size_t)NE * DIM * FFD];     // W2 transposed [e][d][ff]
__device__ int   g_cnt[NE];
__device__ int   g_list[NE * NTOK];
__device__ int   g_tslot[2 * NTOK];                 // per-token (e*NTOK+slot) for top1/top2
__device__ float g_tw[2 * NTOK];                    // per-token combine weights

// ---------------- tf32 helpers ----------------
__device__ __forceinline__ float to_tf32(float x) {
    float r;
    asm("cvt.rna.tf32.f32 %0, %1;" : "=f"(r) : "f"(x));
    return r;
}
__device__ __forceinline__ float4 cvt4(float4 v) {
    v.x = to_tf32(v.x); v.y = to_tf32(v.y); v.z = to_tf32(v.z); v.w = to_tf32(v.w);
    return v;
}

// ---------------- tf32 mma core: 128x64 block tile, 8 warps, BK=16 ----------------
// A rows resolved through rows_s (smem, 128 entries, -1 -> zero row).
// B is [N,K] row-major (K contiguous), ldb given, n0 = block col offset.
__device__ __forceinline__ void mma_core(
    const float* __restrict__ Aptr, int lda,
    const float* __restrict__ Bptr, int ldb, int n0,
    int K, const int* rows_s, float* As, float* Bs,
    float (&acc)[2][4][4])
{
    const int tid = threadIdx.x;
    const int am  = tid & 127;
    const int akq = tid >> 7;          // 0/1: handles k-cols {4aq..} and {4aq+8..}
    const int bn  = tid & 63;
    const int bkq = tid >> 6;          // 0..3
    const int lane = tid & 31, wid = tid >> 5;
    const int wm = wid >> 1, wn = wid & 1;
    const int gid = lane >> 2, tig = lane & 3;

    for (int kt = 0; kt < K; kt += 16) {
        // global loads (float4, 16B aligned by construction)
        int r = rows_s[am];
        float4 a0v = make_float4(0.f, 0.f, 0.f, 0.f), a1v = a0v;
        if (r >= 0) {
            const float* ap = Aptr + (size_t)r * lda + kt + 4 * akq;
            a0v = *(const float4*)(ap);
            a1v = *(const float4*)(ap + 8);
        }
        float4 bv = *(const float4*)(Bptr + (size_t)(n0 + bn) * ldb + kt + 4 * bkq);
        __syncthreads();   // previous tile fully consumed
        *(float4*)(As + am * ALD + 4 * akq)     = cvt4(a0v);
        *(float4*)(As + am * ALD + 4 * akq + 8) = cvt4(a1v);
        *(float4*)(Bs + bn * BLD + 4 * bkq)     = cvt4(bv);
        __syncthreads();
#pragma unroll
        for (int c = 0; c < 2; c++) {
            const int k0 = 8 * c;
            uint32_t af[2][4];
#pragma unroll
            for (int mt = 0; mt < 2; mt++) {
                const float* ab = As + (wm * 32 + mt * 16 + gid) * ALD + k0 + tig;
                af[mt][0] = __float_as_uint(ab[0]);
                af[mt][1] = __float_as_uint(ab[8 * ALD]);
                af[mt][2] = __float_as_uint(ab[4]);
                af[mt][3] = __float_as_uint(ab[8 * ALD + 4]);
            }
#pragma unroll
            for (int nt = 0; nt < 4; nt++) {
                const float* bb = Bs + (wn * 32 + nt * 8 + gid) * BLD + k0 + tig;
                uint32_t b0 = __float_as_uint(bb[0]);
                uint32_t b1 = __float_as_uint(bb[4]);
#pragma unroll
                for (int mt = 0; mt < 2; mt++) {
                    asm volatile(
                        "mma.sync.aligned.m16n8k8.row.col.f32.tf32.tf32.f32 "
                        "{%0,%1,%2,%3},{%4,%5,%6,%7},{%8,%9},{%0,%1,%2,%3};\n"
                        : "+f"(acc[mt][nt][0]), "+f"(acc[mt][nt][1]),
                          "+f"(acc[mt][nt][2]), "+f"(acc[mt][nt][3])
                        : "r"(af[mt][0]), "r"(af[mt][1]), "r"(af[mt][2]), "r"(af[mt][3]),
                          "r"(b0), "r"(b1));
                }
            }
        }
    }
}

#define MMA_PROLOGUE                                    \
    __shared__ float As[128 * ALD];                     \
    __shared__ float Bs[64 * BLD];                      \
    __shared__ int rows_s[128];                         \
    const int tid = threadIdx.x;                        \
    const int lane = tid & 31, wid = tid >> 5;          \
    const int wm = wid >> 1, wn = wid & 1;              \
    const int gid = lane >> 2, tig = lane & 3;          \
    float acc[2][4][4] = {};

// ---------------- projection kernels: C = A @ W^T + bias ----------------
__global__ __launch_bounds__(256) void proj_mma(
    const float* __restrict__ A, const float* __restrict__ W,
    const float* __restrict__ bias, float* __restrict__ C, int vt_mode)
{
    MMA_PROLOGUE
    int m0 = blockIdx.y * 128, n0 = blockIdx.x * 64;
    if (tid < 128) rows_s[tid] = m0 + tid;
    __syncthreads();
    mma_core(A, DIM, W, DIM, n0, DIM, rows_s, As, Bs, acc);
#pragma unroll
    for (int mt = 0; mt < 2; mt++) {
#pragma unroll
        for (int nt = 0; nt < 4; nt++) {
            int row = m0 + wm * 32 + mt * 16 + gid;
            int col = n0 + wn * 32 + nt * 8 + 2 * tig;
            float b0 = bias[col], b1 = bias[col + 1];
            if (vt_mode == 0) {
                float2 v0 = {acc[mt][nt][0] + b0, acc[mt][nt][1] + b1};
                float2 v1 = {acc[mt][nt][2] + b0, acc[mt][nt][3] + b1};
                *(float2*)(C + (size_t)row * DIM + col) = v0;
                *(float2*)(C + (size_t)(row + 8) * DIM + col) = v1;
            } else {
                // write V transposed: Vt[b][h][d][t]
#pragma unroll
                for (int q = 0; q < 4; q++) {
                    int rr = row + (q >> 1) * 8;
                    int cc = col + (q & 1);
                    int bb = rr >> 10, tt = rr & 1023;
                    int h = cc >> 6, d = cc & 63;
                    C[(((size_t)bb * NH + h) * HD + d) * SEQ + tt] =
                        acc[mt][nt][q] + bias[cc];
                }
            }
        }
    }
}

// ---------------- QK^T: g_P[z,q,k] = scale * Q.K ----------------
__global__ __launch_bounds__(256) void qk_mma(
    const float* __restrict__ Q, const float* __restrict__ Kt, float scale)
{
    MMA_PROLOGUE
    int z = blockIdx.z, b = z / NH, h = z % NH;
    int m0 = blockIdx.y * 128, n0 = blockIdx.x * 64;
    if (tid < 128) rows_s[tid] = m0 + tid;
    __syncthreads();
    const float* Ab = Q + (size_t)b * SEQ * DIM + h * HD;
    const float* Bb = Kt + (size_t)b * SEQ * DIM + h * HD;
    float* Cb = g_P + (size_t)z * SEQ * SEQ;
    mma_core(Ab, DIM, Bb, DIM, n0, HD, rows_s, As, Bs, acc);
#pragma unroll
    for (int mt = 0; mt < 2; mt++) {
#pragma unroll
        for (int nt = 0; nt < 4; nt++) {
            int row = m0 + wm * 32 + mt * 16 + gid;
            int col = n0 + wn * 32 + nt * 8 + 2 * tig;
            float2 v0 = {acc[mt][nt][0] * scale, acc[mt][nt][1] * scale};
            float2 v1 = {acc[mt][nt][2] * scale, acc[mt][nt][3] * scale};
            *(float2*)(Cb + (size_t)row * SEQ + col) = v0;
            *(float2*)(Cb + (size_t)(row + 8) * SEQ + col) = v1;
        }
    }
}

// ---------------- P @ V (via Vt): attn[b,q,h*64+d] ----------------
__global__ __launch_bounds__(256) void pv_mma()
{
    MMA_PROLOGUE
    int z = blockIdx.z, b = z / NH, h = z % NH;
    int m0 = blockIdx.y * 128;
    if (tid < 128) rows_s[tid] = m0 + tid;
    __syncthreads();
    const float* Ab = g_P + (size_t)z * SEQ * SEQ;
    const float* Bb = g_Vt + (size_t)z * HD * SEQ;
    mma_core(Ab, SEQ, Bb, SEQ, 0, SEQ, rows_s, As, Bs, acc);
#pragma unroll
    for (int mt = 0; mt < 2; mt++) {
#pragma unroll
        for (int nt = 0; nt < 4; nt++) {
            int row = m0 + wm * 32 + mt * 16 + gid;
            int col = wn * 32 + nt * 8 + 2 * tig;
            float* c0 = g_attn + ((size_t)(b * SEQ + row)) * DIM + h * HD + col;
            float* c1 = g_attn + ((size_t)(b * SEQ + row + 8)) * DIM + h * HD + col;
            *(float2*)c0 = make_float2(acc[mt][nt][0], acc[mt][nt][1]);
            *(float2*)c1 = make_float2(acc[mt][nt][2], acc[mt][nt][3]);
        }
    }
}

// ---------------- FF1: H1 = relu(x[list] @ W1t^T + b1) ----------------
__global__ __launch_bounds__(256) void ff1_mma(
    const float* __restrict__ x, const float* __restrict__ b1)
{
    int e = blockIdx.z;
    int cnt = g_cnt[e];
    int m0 = blockIdx.y * 128;
    if (m0 >= cnt) return;
    MMA_PROLOGUE
    int n0 = blockIdx.x * 64;
    if (tid < 128) rows_s[tid] = (m0 + tid < cnt) ? g_list[e * NTOK + m0 + tid] : -1;
    __syncthreads();
    const float* Bb = g_W1t + (size_t)e * FFD * DIM;
    const float* bb = b1 + e * FFD;
    float* Hout = g_H1 + (size_t)e * NTOK * FFD;
    mma_core(x, DIM, Bb, DIM, n0, DIM, rows_s, As, Bs, acc);
#pragma unroll
    for (int mt = 0; mt < 2; mt++) {
#pragma unroll
        for (int nt = 0; nt < 4; nt++) {
            int lm = m0 + wm * 32 + mt * 16 + gid;
            int col = n0 + wn * 32 + nt * 8 + 2 * tig;
            float b0 = bb[col], b1v = bb[col + 1];
            if (lm < cnt) {
                float2 v = {fmaxf(acc[mt][nt][0] + b0, 0.f), fmaxf(acc[mt][nt][1] + b1v, 0.f)};
                *(float2*)(Hout + (size_t)lm * FFD + col) = v;
            }
            if (lm + 8 < cnt) {
                float2 v = {fmaxf(acc[mt][nt][2] + b0, 0.f), fmaxf(acc[mt][nt][3] + b1v, 0.f)};
                *(float2*)(Hout + (size_t)(lm + 8) * FFD + col) = v;
            }
        }
    }
}

// ---------------- FF2: Y = H1 @ W2t^T + b2 (compact rows) ----------------
__global__ __launch_bounds__(256) void ff2_mma(const float* __restrict__ b2)
{
    int e = blockIdx.z;
    int cnt = g_cnt[e];
    int m0 = blockIdx.y * 128;
    if (m0 >= cnt) return;
    MMA_PROLOGUE
    int n0 = blockIdx.x * 64;
    if (tid < 128) rows_s[tid] = (m0 + tid < cnt) ? (m0 + tid) : -1;
    __syncthreads();
    const float* Ab = g_H1 + (size_t)e * NTOK * FFD;
    const float* Bb = g_W2t + (size_t)e * DIM * FFD;
    const float* bb = b2 + e * DIM;
    float* Yout = g_Y + (size_t)e * NTOK * DIM;
    mma_core(Ab, FFD, Bb, FFD, n0, FFD, rows_s, As, Bs, acc);
#pragma unroll
    for (int mt = 0; mt < 2; mt++) {
#pragma unroll
        for (int nt = 0; nt < 4; nt++) {
            int lm = m0 + wm * 32 + mt * 16 + gid;
            int col = n0 + wn * 32 + nt * 8 + 2 * tig;
            float b0 = bb[col], b1v = bb[col + 1];
            if (lm < cnt) {
                float2 v = {acc[mt][nt][0] + b0, acc[mt][nt][1] + b1v};
                *(float2*)(Yout + (size_t)lm * DIM + col) = v;
            }
            if (lm + 8 < cnt) {
                float2 v = {acc[mt][nt][2] + b0, acc[mt][nt][3] + b1v};
                *(float2*)(Yout + (size_t)(lm + 8) * DIM + col) = v;
            }
        }
    }
}

// ---------------- weight transpose: out[c][r] = in[r][c], per expert slice ----------------
__global__ void transpose_k(const float* __restrict__ in, float* __restrict__ out,
                            int R, int C)
{
    __shared__ float t[32][33];
    int e = blockIdx.z;
    in += (size_t)e * R * C;
    out += (size_t)e * R * C;
    int c0 = blockIdx.x * 32, r0 = blockIdx.y * 32;
    int tx = threadIdx.x, ty = threadIdx.y;
#pragma unroll
    for (int i = 0; i < 32; i += 8)
        t[ty + i][tx] = in[(size_t)(r0 + ty + i) * C + c0 + tx];
    __syncthreads();
#pragma unroll
    for (int i = 0; i < 32; i += 8)
        out[(size_t)(c0 + ty + i) * R + r0 + tx] = t[tx][ty + i];
}

// ---------------- reductions ----------------
__device__ __forceinline__ float blockReduceSum(float v) {
    __shared__ float red[8];
    int lane = threadIdx.x & 31, wid = threadIdx.x >> 5;
#pragma unroll
    for (int o = 16; o > 0; o >>= 1) v += __shfl_xor_sync(0xffffffffu, v, o);
    __syncthreads();
    if (lane == 0) red[wid] = v;
    __syncthreads();
    float r = (lane < 8) ? red[lane] : 0.f;
#pragma unroll
    for (int o = 16; o > 0; o >>= 1) r += __shfl_xor_sync(0xffffffffu, r, o);
    return r;
}
__device__ __forceinline__ float blockReduceMax(float v) {
    __shared__ float redm[8];
    int lane = threadIdx.x & 31, wid = threadIdx.x >> 5;
#pragma unroll
    for (int o = 16; o > 0; o >>= 1) v = fmaxf(v, __shfl_xor_sync(0xffffffffu, v, o));
    __syncthreads();
    if (lane == 0) redm[wid] = v;
    __syncthreads();
    float r = (lane < 8) ? redm[lane] : -1e30f;
#pragma unroll
    for (int o = 16; o > 0; o >>= 1) r = fmaxf(r, __shfl_xor_sync(0xffffffffu, r, o));
    return r;
}

// ---------------- zscore (ddof=1) + gamma + softmax, in place over g_P rows ----------------
__global__ void zsoftmax_kernel(const float* __restrict__ gamma) {
    int q = blockIdx.x, z = blockIdx.y;
    float* row = g_P + ((size_t)z * SEQ + q) * SEQ;
    int tid = threadIdx.x;
    float v[4];
#pragma unroll
    for (int i = 0; i < 4; i++) v[i] = row[tid + i * 256];
    float mean = blockReduceSum(v[0] + v[1] + v[2] + v[3]) * (1.f / SEQ);
    float sq = 0.f;
#pragma unroll
    for (int i = 0; i < 4; i++) { v[i] -= mean; sq += v[i] * v[i]; }
    float var = blockReduceSum(sq) * (1.f / (SEQ - 1));
    float inv = (*gamma) / (sqrtf(var) + EPSZ);
    float mx = -1e30f;
#pragma unroll
    for (int i = 0; i < 4; i++) { v[i] *= inv; mx = fmaxf(mx, v[i]); }
    mx = blockReduceMax(mx);
    float es = 0.f;
#pragma unroll
    for (int i = 0; i < 4; i++) { v[i] = __expf(v[i] - mx); es += v[i]; }
    es = blockReduceSum(es);
    float r = 1.f / es;
#pragma unroll
    for (int i = 0; i < 4; i++) row[tid + i * 256] = v[i] * r;
}

// ---------------- LN1: x = LN(a + b) ----------------
__global__ void add_ln_kernel(const float* __restrict__ a, const float* __restrict__ b,
                              const float* __restrict__ g, const float* __restrict__ be,
                              float* __restrict__ out) {
    int t = blockIdx.x, tid = threadIdx.x;
    const float* ar = a + (size_t)t * DIM;
    const float* br = b + (size_t)t * DIM;
    float v[3];
#pragma unroll
    for (int i = 0; i < 3; i++) v[i] = ar[tid + i * 256] + br[tid + i * 256];
    float mean = blockReduceSum(v[0] + v[1] + v[2]) * (1.f / DIM);
    float sq = 0.f;
#pragma unroll
    for (int i = 0; i < 3; i++) { v[i] -= mean; sq += v[i] * v[i]; }
    float var = blockReduceSum(sq) * (1.f / DIM);
    float r = rsqrtf(var + EPSLN);
#pragma unroll
    for (int i = 0; i < 3; i++) {
        int c = tid + i * 256;
        out[(size_t)t * DIM + c] = v[i] * r * g[c] + be[c];
    }
}

// ---------------- LN2 with MoE combine: out = LN(x + w1*Y[s1] + w2*Y[s2]) ----------------
__global__ void add_ln2_moe_kernel(const float* __restrict__ x,
                                   const float* __restrict__ g, const float* __restrict__ be,
                                   float* __restrict__ out) {
    int t = blockIdx.x, tid = threadIdx.x;
    int s1 = g_tslot[t], s2 = g_tslot[NTOK + t];
    float w1 = g_tw[t], w2 = g_tw[NTOK + t];
    const float* y1 = g_Y + (size_t)s1 * DIM;
    const float* y2 = g_Y + (size_t)s2 * DIM;
    const float* xr = x + (size_t)t * DIM;
    float v[3];
#pragma unroll
    for (int i = 0; i < 3; i++) {
        int c = tid + i * 256;
        v[i] = xr[c] + w1 * y1[c] + w2 * y2[c];
    }
    float mean = blockReduceSum(v[0] + v[1] + v[2]) * (1.f / DIM);
    float sq = 0.f;
#pragma unroll
    for (int i = 0; i < 3; i++) { v[i] -= mean; sq += v[i] * v[i]; }
    float var = blockReduceSum(sq) * (1.f / DIM);
    float r = rsqrtf(var + EPSLN);
#pragma unroll
    for (int i = 0; i < 3; i++) {
        int c = tid + i * 256;
        out[(size_t)t * DIM + c] = v[i] * r * g[c] + be[c];
    }
}

// ---------------- routing counters ----------------
__global__ void zero_cnt_kernel() {
    if (threadIdx.x < NE) g_cnt[threadIdx.x] = 0;
}

// ---------------- gating: softmax over E=4, top-2, build routing lists ----------------
__global__ void gate_kernel(const float* __restrict__ x, const float* __restrict__ Wg,
                            const float* __restrict__ bg) {
    int tok = (blockIdx.x * blockDim.x + threadIdx.x) >> 5;
    int lane = threadIdx.x & 31;
    if (tok >= NTOK) return;
    const float* xr = x + (size_t)tok * DIM;
    float s0 = 0, s1 = 0, s2 = 0, s3 = 0;
    for (int d = lane; d < DIM; d += 32) {
        float xv = xr[d];
        s0 += xv * Wg[d];
        s1 += xv * Wg[DIM + d];
        s2 += xv * Wg[2 * DIM + d];
        s3 += xv * Wg[3 * DIM + d];
    }
#pragma unroll
    for (int o = 16; o > 0; o >>= 1) {
        s0 += __shfl_xor_sync(0xffffffffu, s0, o);
        s1 += __shfl_xor_sync(0xffffffffu, s1, o);
        s2 += __shfl_xor_sync(0xffffffffu, s2, o);
        s3 += __shfl_xor_sync(0xffffffffu, s3, o);
    }
    if (lane == 0) {
        float s[4] = {s0 + bg[0], s1 + bg[1], s2 + bg[2], s3 + bg[3]};
        float mx = fmaxf(fmaxf(s[0], s[1]), fmaxf(s[2], s[3]));
        float p[4], sum = 0.f;
#pragma unroll
        for (int e = 0; e < 4; e++) { p[e] = expf(s[e] - mx); sum += p[e]; }
        float r = 1.f / sum;
#pragma unroll
        for (int e = 0; e < 4; e++) p[e] *= r;
        int i1 = 0;
#pragma unroll
        for (int e = 1; e < 4; e++) if (p[e] > p[i1]) i1 = e;
        int i2 = (i1 == 0) ? 1 : 0;
#pragma unroll
        for (int e = 0; e < 4; e++) if (e != i1 && p[e] > p[i2]) i2 = e;
        int slot = atomicAdd(&g_cnt[i1], 1);
        g_list[i1 * NTOK + slot] = tok;
        g_tslot[tok] = i1 * NTOK + slot;
        g_tw[tok] = p[i1];
        slot = atomicAdd(&g_cnt[i2], 1);
        g_list[i2 * NTOK + slot] = tok;
        g_tslot[NTOK + tok] = i2 * NTOK + slot;
        g_tw[NTOK + tok] = p[i2];
    }
}

// ---------------- launch ----------------
extern "C" void kernel_launch(void* const* d_in, const int* in_sizes, int n_in,
                              void* d_out, int out_size) {
    const float* src  = (const float*)d_in[0];
    // d_in[1] = frac (unused: add_frac_bias=False path)
    const float* Wq = (const float*)d_in[2];
    const float* bq = (const float*)d_in[3];
    const float* Wk = (const float*)d_in[4];
    const float* bk = (const float*)d_in[5];
    const float* Wv = (const float*)d_in[6];
    const float* bv = (const float*)d_in[7];
    const float* Wo = (const float*)d_in[8];
    const float* bo = (const float*)d_in[9];
    const float* gamma = (const float*)d_in[10];
    const float* ln1g = (const float*)d_in[11];
    const float* ln1b = (const float*)d_in[12];
    const float* ln2g = (const float*)d_in[13];
    const float* ln2b = (const float*)d_in[14];
    const float* Wg = (const float*)d_in[15];
    const float* bg = (const float*)d_in[16];
    const float* W1 = (const float*)d_in[17];
    const float* b1 = (const float*)d_in[18];
    const float* W2 = (const float*)d_in[19];
    const float* b2 = (const float*)d_in[20];
    float* out = (float*)d_out;

    float *Qp, *Kp, *Vtp, *attnp, *attnop, *xp, *W1tp, *W2tp;
    cudaGetSymbolAddress((void**)&Qp, g_Q);
    cudaGetSymbolAddress((void**)&Kp, g_K);
    cudaGetSymbolAddress((void**)&Vtp, g_Vt);
    cudaGetSymbolAddress((void**)&attnp, g_attn);
    cudaGetSymbolAddress((void**)&attnop, g_attno);
    cudaGetSymbolAddress((void**)&xp, g_x);
    cudaGetSymbolAddress((void**)&W1tp, g_W1t);
    cudaGetSymbolAddress((void**)&W2tp, g_W2t);

    zero_cnt_kernel<<<1, 32>>>();

    // weight transposes (NT fast path for FF GEMMs)
    transpose_k<<<dim3(FFD / 32, DIM / 32, NE), dim3(32, 8)>>>(W1, W1tp, DIM, FFD);
    transpose_k<<<dim3(DIM / 32, FFD / 32, NE), dim3(32, 8)>>>(W2, W2tp, FFD, DIM);

    // QKV projections (V written transposed)
    dim3 gproj(DIM / 64, NTOK / 128);
    proj_mma<<<gproj, 256>>>(src, Wq, bq, Qp, 0);
    proj_mma<<<gproj, 256>>>(src, Wk, bk, Kp, 0);
    proj_mma<<<gproj, 256>>>(src, Wv, bv, Vtp, 1);

    // logits = scale * Q K^T
    qk_mma<<<dim3(SEQ / 64, SEQ / 128, BHZ), 256>>>(Qp, Kp, 0.125f);

    // zscore + gamma + softmax
    zsoftmax_kernel<<<dim3(SEQ, BHZ), 256>>>(gamma);

    // attn = P @ V
    pv_mma<<<dim3(1, SEQ / 128, BHZ), 256>>>();

    // O projection
    proj_mma<<<gproj, 256>>>(attnp, Wo, bo, attnop, 0);

    // x = LN1(src + attn_out)
    add_ln_kernel<<<NTOK, 256>>>(src, attnop, ln1g, ln1b, xp);

    // gating + routing
    gate_kernel<<<NTOK * 32 / 256, 256>>>(xp, Wg, bg);

    // expert FFN (sparse top-2)
    ff1_mma<<<dim3(FFD / 64, NTOK / 128, NE), 256>>>(xp, b1);
    ff2_mma<<<dim3(DIM / 64, NTOK / 128, NE), 256>>>(b2);

    // out = LN2(x + combine(Y))
    add_ln2_moe_kernel<<<NTOK, 256>>>(xp, ln2g, ln2b, out);
}